// round 1
// baseline (speedup 1.0000x reference)
#include <cuda_runtime.h>
#include <math.h>

// ---------------- problem constants ----------------
#define BB 4
#define NN 32768
#define CC 256
#define HH 8
#define DD 32
#define GG 64
#define HID 1024
#define BN (BB * NN)          // 131072 tokens

// ---------------- scratch (device globals; no allocation allowed) ----------
__device__ float g_h[BN * CC];        // LN1 output, reused for LN2 output
__device__ float g_fxmid[BN * CC];    // fx_mid, reused for fx2 (post-attn residual)
__device__ float g_xmid[BN * CC];     // x_mid, reused for out_x
__device__ float g_sw[(size_t)BN * HH * GG];   // slice weights [B,H,N,G]
__device__ float g_hid[(size_t)BN * HID];      // MLP hidden
__device__ float g_tok[BB * HH * GG * DD];     // slice tokens (atomic accum)
__device__ float g_nrm[BB * HH * GG];          // slice norms (atomic accum)
__device__ float g_ot[BB * HH * GG * DD];      // attention output tokens

// ---------------- LayerNorm: one block per row, 256 threads ----------------
__global__ void __launch_bounds__(256) ln_kernel(
    const float* __restrict__ x, const float* __restrict__ g,
    const float* __restrict__ b, float* __restrict__ out)
{
    size_t row = blockIdx.x;
    int t = threadIdx.x;
    float v = x[row * CC + t];
    float s = v, s2 = v * v;
    #pragma unroll
    for (int o = 16; o > 0; o >>= 1) {
        s  += __shfl_xor_sync(0xffffffffu, s,  o);
        s2 += __shfl_xor_sync(0xffffffffu, s2, o);
    }
    __shared__ float ws[8], ws2[8];
    int w = t >> 5, l = t & 31;
    if (l == 0) { ws[w] = s; ws2[w] = s2; }
    __syncthreads();
    float sum = 0.f, sum2 = 0.f;
    #pragma unroll
    for (int i = 0; i < 8; i++) { sum += ws[i]; sum2 += ws2[i]; }
    float m   = sum * (1.0f / CC);
    float var = sum2 * (1.0f / CC) - m * m;
    float inv = rsqrtf(var + 1e-5f);
    out[row * CC + t] = (v - m) * inv * g[t] + b[t];
}

// ---------------- generic fp32 GEMM: C = A[M,K]@B[K,N] + bias (+res)(gelu) --
// 64x64 block tile, BK=16, 256 threads, 4x4 per thread
__device__ __forceinline__ float gelu_f(float x) {
    return 0.5f * x * (1.0f + erff(x * 0.70710678118654752f));
}

__global__ void __launch_bounds__(256) gemm_kernel(
    const float* __restrict__ A, const float* __restrict__ Bm,
    const float* __restrict__ bias, const float* __restrict__ res,
    float* __restrict__ Cc, int M, int N, int K, int act)
{
    __shared__ float As[16][64];
    __shared__ float Bs[16][64];
    int bx = blockIdx.x, by = blockIdx.y;
    int tid = threadIdx.x;
    int tx = tid & 15, ty = tid >> 4;

    float acc[4][4];
    #pragma unroll
    for (int i = 0; i < 4; i++)
        #pragma unroll
        for (int j = 0; j < 4; j++) acc[i][j] = 0.f;

    int am = tid >> 2;            // row within tile 0..63
    int ak = (tid & 3) * 4;       // k within tile {0,4,8,12}
    int bk = tid >> 4;            // k within tile 0..15
    int bn = (tid & 15) * 4;      // col within tile

    const float* Aptr = A + (size_t)(by * 64 + am) * K + ak;
    const float* Bptr = Bm + (size_t)bk * N + bx * 64 + bn;

    for (int k0 = 0; k0 < K; k0 += 16) {
        float4 a4 = *(const float4*)(Aptr + k0);
        float4 b4 = *(const float4*)(Bptr + (size_t)k0 * N);
        As[ak + 0][am] = a4.x; As[ak + 1][am] = a4.y;
        As[ak + 2][am] = a4.z; As[ak + 3][am] = a4.w;
        *(float4*)&Bs[bk][bn] = b4;
        __syncthreads();
        #pragma unroll
        for (int k = 0; k < 16; k++) {
            float4 av = *(const float4*)&As[k][ty * 4];
            float4 bv = *(const float4*)&Bs[k][tx * 4];
            float a[4] = {av.x, av.y, av.z, av.w};
            float b[4] = {bv.x, bv.y, bv.z, bv.w};
            #pragma unroll
            for (int i = 0; i < 4; i++)
                #pragma unroll
                for (int j = 0; j < 4; j++) acc[i][j] += a[i] * b[j];
        }
        __syncthreads();
    }

    int row0 = by * 64 + ty * 4;
    int col0 = bx * 64 + tx * 4;
    float4 bb = *(const float4*)&bias[col0];
    #pragma unroll
    for (int i = 0; i < 4; i++) {
        size_t off = (size_t)(row0 + i) * N + col0;
        float4 c = make_float4(acc[i][0] + bb.x, acc[i][1] + bb.y,
                               acc[i][2] + bb.z, acc[i][3] + bb.w);
        if (res) {
            float4 r = *(const float4*)&res[off];
            c.x += r.x; c.y += r.y; c.z += r.z; c.w += r.w;
        }
        if (act) {
            c.x = gelu_f(c.x); c.y = gelu_f(c.y);
            c.z = gelu_f(c.z); c.w = gelu_f(c.w);
        }
        *(float4*)&Cc[off] = c;
    }
}

// ---------------- slice softmax: one warp per (token, head) ----------------
__global__ void __launch_bounds__(128) slice_softmax_kernel(
    const float* __restrict__ xmid, const float* __restrict__ wsl,
    const float* __restrict__ bsl, const float* __restrict__ temp,
    float* __restrict__ sw)
{
    __shared__ float ws[32][64];
    int t = threadIdx.x;
    for (int i = t; i < DD * GG; i += 128) ws[i >> 6][i & 63] = wsl[i];
    __syncthreads();
    int warp = t >> 5, lane = t & 31;
    size_t task = (size_t)blockIdx.x * 4 + warp;   // < BN*H
    int head = (int)(task & 7);
    size_t token = task >> 3;
    float x = xmid[token * CC + head * DD + lane];
    float l0 = bsl[lane], l1 = bsl[lane + 32];
    #pragma unroll
    for (int d = 0; d < 32; d++) {
        float xd = __shfl_sync(0xffffffffu, x, d);
        l0 += xd * ws[d][lane];
        l1 += xd * ws[d][lane + 32];
    }
    float it = 1.0f / temp[head];
    l0 *= it; l1 *= it;
    float mx = fmaxf(l0, l1);
    #pragma unroll
    for (int o = 16; o > 0; o >>= 1) mx = fmaxf(mx, __shfl_xor_sync(0xffffffffu, mx, o));
    float e0 = expf(l0 - mx), e1 = expf(l1 - mx);
    float s = e0 + e1;
    #pragma unroll
    for (int o = 16; o > 0; o >>= 1) s += __shfl_xor_sync(0xffffffffu, s, o);
    float inv = 1.0f / s;
    int b = (int)(token >> 15);
    int n = (int)(token & (NN - 1));
    size_t base = (((size_t)b * HH + head) * NN + n) * GG;
    sw[base + lane]      = e0 * inv;
    sw[base + 32 + lane] = e1 * inv;
}

// ---------------- zero accumulators ----------------
__global__ void zero_kernel() {
    int i = blockIdx.x * blockDim.x + threadIdx.x;
    if (i < BB * HH * GG * DD) g_tok[i] = 0.f;
    if (i < BB * HH * GG)      g_nrm[i] = 0.f;
}

// ---------------- slice_token accumulation: [G,D] += sw^T @ fx_mid ---------
// grid: (chunks, B*H), 256 threads; each thread owns (2 g) x (4 d)
__global__ void __launch_bounds__(256) slice_token_kernel(
    const float* __restrict__ fxmid, const float* __restrict__ sw)
{
    const int CH = 2048, NB = 32;
    int bh = blockIdx.y;
    int b = bh >> 3, h = bh & 7;
    int nbase = blockIdx.x * CH;
    int t = threadIdx.x;
    int gp = t >> 3;          // 0..31 -> g0 = gp, g1 = gp+32
    int dq = t & 7;
    int d0 = dq * 4;
    __shared__ float sws[NB][64];
    __shared__ float fxs[NB][32];
    float a0[4] = {0, 0, 0, 0}, a1[4] = {0, 0, 0, 0};
    float n0 = 0.f, n1 = 0.f;
    size_t swbase = (size_t)bh * NN * GG;
    size_t fxbase = (size_t)b * NN * CC + h * DD;
    for (int nb = 0; nb < CH; nb += NB) {
        __syncthreads();
        for (int i = t; i < NB * 16; i += 256) {
            int nn = i >> 4, c4 = (i & 15) * 4;
            *(float4*)&sws[nn][c4] =
                *(const float4*)&sw[swbase + (size_t)(nbase + nb + nn) * GG + c4];
        }
        for (int i = t; i < NB * 8; i += 256) {
            int nn = i >> 3, c4 = (i & 7) * 4;
            *(float4*)&fxs[nn][c4] =
                *(const float4*)&fxmid[fxbase + (size_t)(nbase + nb + nn) * CC + c4];
        }
        __syncthreads();
        #pragma unroll 4
        for (int nn = 0; nn < NB; nn++) {
            float s0 = sws[nn][gp], s1 = sws[nn][gp + 32];
            float4 f = *(const float4*)&fxs[nn][d0];
            a0[0] += s0 * f.x; a0[1] += s0 * f.y; a0[2] += s0 * f.z; a0[3] += s0 * f.w;
            a1[0] += s1 * f.x; a1[1] += s1 * f.y; a1[2] += s1 * f.z; a1[3] += s1 * f.w;
            if (dq == 0) { n0 += s0; n1 += s1; }
        }
    }
    size_t tb = (size_t)bh * GG * DD;
    #pragma unroll
    for (int j = 0; j < 4; j++) {
        atomicAdd(&g_tok[tb + gp * DD + d0 + j],        a0[j]);
        atomicAdd(&g_tok[tb + (gp + 32) * DD + d0 + j], a1[j]);
    }
    if (dq == 0) {
        atomicAdd(&g_nrm[bh * GG + gp],      n0);
        atomicAdd(&g_nrm[bh * GG + gp + 32], n1);
    }
}

// ---------------- tiny attention over G=64 slice tokens --------------------
__global__ void __launch_bounds__(64) attn_kernel(
    const float* __restrict__ wq, const float* __restrict__ wk,
    const float* __restrict__ wv)
{
    int bh = blockIdx.x;
    int g = threadIdx.x;   // 0..63
    __shared__ float st[64][33];
    __shared__ float ks2[64][33];
    __shared__ float vs[64][33];
    __shared__ float wqs[32][32], wks[32][32], wvs[32][32];
    for (int i = g; i < 1024; i += 64) {
        wqs[i >> 5][i & 31] = wq[i];
        wks[i >> 5][i & 31] = wk[i];
        wvs[i >> 5][i & 31] = wv[i];
    }
    float nv = g_nrm[bh * GG + g] + 1e-5f;
    float invn = 1.0f / nv;
    #pragma unroll
    for (int d = 0; d < 32; d++)
        st[g][d] = g_tok[((size_t)bh * GG + g) * DD + d] * invn;
    __syncthreads();
    float q[32];
    #pragma unroll 4
    for (int dout = 0; dout < 32; dout++) {
        float sq = 0.f, sk = 0.f, sv = 0.f;
        #pragma unroll
        for (int di = 0; di < 32; di++) {
            float s = st[g][di];
            sq += s * wqs[di][dout];
            sk += s * wks[di][dout];
            sv += s * wvs[di][dout];
        }
        q[dout] = sq; ks2[g][dout] = sk; vs[g][dout] = sv;
    }
    __syncthreads();
    float sc[64];
    float mx = -1e30f;
    const float scale = 0.17677669529663687f;   // 1/sqrt(32)
    #pragma unroll 4
    for (int kk = 0; kk < 64; kk++) {
        float s = 0.f;
        #pragma unroll
        for (int d = 0; d < 32; d++) s += q[d] * ks2[kk][d];
        s *= scale;
        sc[kk] = s;
        mx = fmaxf(mx, s);
    }
    float sum = 0.f;
    #pragma unroll 4
    for (int kk = 0; kk < 64; kk++) { sc[kk] = expf(sc[kk] - mx); sum += sc[kk]; }
    float inv = 1.0f / sum;
    #pragma unroll 4
    for (int d = 0; d < 32; d++) {
        float o = 0.f;
        #pragma unroll
        for (int kk = 0; kk < 64; kk++) o += sc[kk] * vs[kk][d];
        g_ot[((size_t)bh * GG + g) * DD + d] = o * inv;
    }
}

// ---------------- de-slice: out_x[n, h*32+d] = sum_g sw[n,g] * ot[g,d] -----
// grid: (N/32, B*H), 256 threads; 8 threads per token x 4 d each
__global__ void __launch_bounds__(256) deslice_kernel(
    const float* __restrict__ sw, float* __restrict__ outx)
{
    int bh = blockIdx.y;
    int b = bh >> 3, h = bh & 7;
    int nbase = blockIdx.x * 32;
    int t = threadIdx.x;
    int tt = t >> 3, dq = t & 7, d0 = dq * 4;
    __shared__ float ots[64][32];
    __shared__ float sws[32][64];
    for (int i = t; i < 512; i += 256) {
        int g = i >> 3, c4 = (i & 7) * 4;
        *(float4*)&ots[g][c4] = *(const float4*)&g_ot[((size_t)bh * GG + g) * DD + c4];
    }
    for (int i = t; i < 512; i += 256) {
        int nn = i >> 4, c4 = (i & 15) * 4;
        *(float4*)&sws[nn][c4] =
            *(const float4*)&sw[((size_t)bh * NN + nbase + nn) * GG + c4];
    }
    __syncthreads();
    float acc[4] = {0, 0, 0, 0};
    #pragma unroll 8
    for (int g = 0; g < 64; g++) {
        float s = sws[tt][g];
        float4 f = *(const float4*)&ots[g][d0];
        acc[0] += s * f.x; acc[1] += s * f.y; acc[2] += s * f.z; acc[3] += s * f.w;
    }
    size_t o = ((size_t)b * NN + nbase + tt) * CC + h * DD + d0;
    *(float4*)&outx[o] = make_float4(acc[0], acc[1], acc[2], acc[3]);
}

// ---------------- launch ----------------
extern "C" void kernel_launch(void* const* d_in, const int* in_sizes, int n_in,
                              void* d_out, int out_size)
{
    const float* fx     = (const float*)d_in[0];
    const float* ln1_g  = (const float*)d_in[1];
    const float* ln1_b  = (const float*)d_in[2];
    const float* w_fx   = (const float*)d_in[3];
    const float* b_fx   = (const float*)d_in[4];
    const float* w_x    = (const float*)d_in[5];
    const float* b_x    = (const float*)d_in[6];
    const float* w_sl   = (const float*)d_in[7];
    const float* b_sl   = (const float*)d_in[8];
    const float* temp   = (const float*)d_in[9];
    const float* w_q    = (const float*)d_in[10];
    const float* w_k    = (const float*)d_in[11];
    const float* w_v    = (const float*)d_in[12];
    const float* w_o    = (const float*)d_in[13];
    const float* b_o    = (const float*)d_in[14];
    const float* ln2_g  = (const float*)d_in[15];
    const float* ln2_b  = (const float*)d_in[16];
    const float* w1     = (const float*)d_in[17];
    const float* b1     = (const float*)d_in[18];
    const float* w2     = (const float*)d_in[19];
    const float* b2     = (const float*)d_in[20];
    float* out = (float*)d_out;

    float *p_h, *p_fxmid, *p_xmid, *p_sw, *p_hid;
    cudaGetSymbolAddress((void**)&p_h,     g_h);
    cudaGetSymbolAddress((void**)&p_fxmid, g_fxmid);
    cudaGetSymbolAddress((void**)&p_xmid,  g_xmid);
    cudaGetSymbolAddress((void**)&p_sw,    g_sw);
    cudaGetSymbolAddress((void**)&p_hid,   g_hid);

    // 1. LN1
    ln_kernel<<<BN, 256>>>(fx, ln1_g, ln1_b, p_h);
    // 2-3. projections
    gemm_kernel<<<dim3(CC / 64, BN / 64), 256>>>(p_h, w_fx, b_fx, nullptr, p_fxmid, BN, CC, CC, 0);
    gemm_kernel<<<dim3(CC / 64, BN / 64), 256>>>(p_h, w_x,  b_x,  nullptr, p_xmid,  BN, CC, CC, 0);
    // 4. zero slice accumulators
    zero_kernel<<<(BB * HH * GG * DD + 255) / 256, 256>>>();
    // 5. slice softmax
    slice_softmax_kernel<<<(BN * HH) / 4, 128>>>(p_xmid, w_sl, b_sl, temp, p_sw);
    // 6. slice token accumulation
    slice_token_kernel<<<dim3(NN / 2048, BB * HH), 256>>>(p_fxmid, p_sw);
    // 7. tiny attention over slice tokens
    attn_kernel<<<BB * HH, 64>>>(w_q, w_k, w_v);
    // 8. de-slice (out_x written into g_xmid, no longer needed)
    deslice_kernel<<<dim3(NN / 32, BB * HH), 256>>>(p_sw, p_xmid);
    // 9. attn_out = out_x @ w_o + b_o + fx  -> fx2 (into g_fxmid)
    gemm_kernel<<<dim3(CC / 64, BN / 64), 256>>>(p_xmid, w_o, b_o, fx, p_fxmid, BN, CC, CC, 0);
    // 10. LN2 (into g_h)
    ln_kernel<<<BN, 256>>>(p_fxmid, ln2_g, ln2_b, p_h);
    // 11. MLP up + gelu
    gemm_kernel<<<dim3(HID / 64, BN / 64), 256>>>(p_h, w1, b1, nullptr, p_hid, BN, HID, CC, 1);
    // 12. MLP down + bias + residual fx2 -> out
    gemm_kernel<<<dim3(CC / 64, BN / 64), 256>>>(p_hid, w2, b2, p_fxmid, out, BN, CC, HID, 0);
}

// round 4
// speedup vs baseline: 1.5607x; 1.5607x over previous
#include <cuda_runtime.h>
#include <cuda_bf16.h>
#include <math.h>
#include <stdint.h>

// ---------------- problem constants ----------------
#define BB 4
#define NN 32768
#define CC 256
#define HH 8
#define DD 32
#define GG 64
#define HID 1024
#define BN (BB * NN)          // 131072 tokens

// ---------------- scratch (device globals) ----------------
__device__ __nv_bfloat16 g_h_hi[(size_t)BN * CC];
__device__ __nv_bfloat16 g_h_lo[(size_t)BN * CC];
__device__ float g_fxmid[(size_t)BN * CC];
__device__ float g_xmid[(size_t)BN * CC];
__device__ float g_sw[(size_t)BN * HH * GG];
__device__ __nv_bfloat16 g_ox_hi[(size_t)BN * CC];
__device__ __nv_bfloat16 g_ox_lo[(size_t)BN * CC];
__device__ float g_fx2[(size_t)BN * CC];
__device__ __nv_bfloat16 g_hid_hi[(size_t)BN * HID];
__device__ __nv_bfloat16 g_hid_lo[(size_t)BN * HID];
__device__ float g_tok[BB * HH * GG * DD];
__device__ float g_nrm[BB * HH * GG];
__device__ float g_ot[BB * HH * GG * DD];
// transposed bf16 hi/lo weights, [N,K] row-major, concatenated
#define WFX_OFF 0
#define WX_OFF  65536
#define WO_OFF  131072
#define W1_OFF  196608
#define W2_OFF  458752
#define WT_TOTAL 720896
__device__ __nv_bfloat16 g_wt_hi[WT_TOTAL];
__device__ __nv_bfloat16 g_wt_lo[WT_TOTAL];

__device__ __forceinline__ float gelu_f(float x) {
    return 0.5f * x * (1.0f + erff(x * 0.70710678118654752f));
}

// ---------------- HMMA hi/lo GEMM ----------------
// C[M,N] = A[M,K] @ B[N,K]^T (+bias)(+res)(gelu)
// A: bf16 hi/lo [M,K] row-major.  B: bf16 hi/lo [N,K] row-major.
// Block tile 128x128, 512 threads = 16 warps (4x4), warp tile 32x32.
// K staged in chunks of 32 into padded SMEM (40 elems = 80B per row:
// LDS bank base (20r+tg) mod 32 is conflict-free across the 8x4 lane grid).
#define KC 32
#define PAD 40   // bf16 elems per padded SMEM row

__device__ __forceinline__ void mma16816(
    float& c0, float& c1, float& c2, float& c3,
    uint32_t a0, uint32_t a1, uint32_t a2, uint32_t a3,
    uint32_t b0, uint32_t b1)
{
    asm volatile(
        "mma.sync.aligned.m16n8k16.row.col.f32.bf16.bf16.f32 "
        "{%0,%1,%2,%3}, {%4,%5,%6,%7}, {%8,%9}, {%0,%1,%2,%3};"
        : "+f"(c0), "+f"(c1), "+f"(c2), "+f"(c3)
        : "r"(a0), "r"(a1), "r"(a2), "r"(a3), "r"(b0), "r"(b1));
}

__global__ void __launch_bounds__(512) hmma_gemm(
    const __nv_bfloat16* __restrict__ Ahi, const __nv_bfloat16* __restrict__ Alo,
    const __nv_bfloat16* __restrict__ Bhi, const __nv_bfloat16* __restrict__ Blo,
    const float* __restrict__ bias, const float* __restrict__ res,
    float* __restrict__ outf, __nv_bfloat16* __restrict__ ohi,
    __nv_bfloat16* __restrict__ olo, int N, int K, int do_gelu)
{
    __shared__ __nv_bfloat16 sAh[128 * PAD], sAl[128 * PAD];
    __shared__ __nv_bfloat16 sBh[128 * PAD], sBl[128 * PAD];

    int t = threadIdx.x, lane = t & 31, wid = t >> 5;
    int wm = wid & 3, wn = wid >> 2;           // warp (m,n) coords in 4x4
    int gid = lane >> 2, tg = lane & 3;
    int row0 = blockIdx.y * 128, col0 = blockIdx.x * 128;

    float acc[2][4][4];
    #pragma unroll
    for (int mi = 0; mi < 2; mi++)
        #pragma unroll
        for (int ni = 0; ni < 4; ni++)
            #pragma unroll
            for (int j = 0; j < 4; j++) acc[mi][ni][j] = 0.f;

    const uint32_t* uAh = (const uint32_t*)sAh;
    const uint32_t* uAl = (const uint32_t*)sAl;
    const uint32_t* uBh = (const uint32_t*)sBh;
    const uint32_t* uBl = (const uint32_t*)sBl;

    for (int k0 = 0; k0 < K; k0 += KC) {
        __syncthreads();
        // stage 128x32 of each tensor; 4B copies, dst pad-safe
        #pragma unroll
        for (int i = 0; i < 4; i++) {
            int idx = t + i * 512;
            int r = idx >> 4, cu = idx & 15;       // 16 uints (32 bf16) per row
            int so = r * (PAD / 2) + cu;           // uint index into SMEM row
            size_t ga = (size_t)(row0 + r) * K + k0 + cu * 2;
            size_t gb = (size_t)(col0 + r) * K + k0 + cu * 2;
            ((uint32_t*)sAh)[so] = *(const uint32_t*)(Ahi + ga);
            ((uint32_t*)sAl)[so] = *(const uint32_t*)(Alo + ga);
            ((uint32_t*)sBh)[so] = *(const uint32_t*)(Bhi + gb);
            ((uint32_t*)sBl)[so] = *(const uint32_t*)(Blo + gb);
        }
        __syncthreads();

        #pragma unroll
        for (int ks = 0; ks < 2; ks++) {
            int kreg = ks * 8 + tg;                // uint col within row
            // B fragments for this warp's 4 n-atoms
            uint32_t bh[4][2], bl[4][2];
            #pragma unroll
            for (int ni = 0; ni < 4; ni++) {
                int nrow = wn * 32 + ni * 8 + gid;
                int o = nrow * (PAD / 2) + kreg;
                bh[ni][0] = uBh[o];     bh[ni][1] = uBh[o + 4];
                bl[ni][0] = uBl[o];     bl[ni][1] = uBl[o + 4];
            }
            #pragma unroll
            for (int mi = 0; mi < 2; mi++) {
                int mrow = wm * 32 + mi * 16 + gid;
                int o0 = mrow * (PAD / 2) + kreg;
                int o1 = (mrow + 8) * (PAD / 2) + kreg;
                uint32_t ah0 = uAh[o0], ah1 = uAh[o1];
                uint32_t ah2 = uAh[o0 + 4], ah3 = uAh[o1 + 4];
                uint32_t al0 = uAl[o0], al1 = uAl[o1];
                uint32_t al2 = uAl[o0 + 4], al3 = uAl[o1 + 4];
                #pragma unroll
                for (int ni = 0; ni < 4; ni++) {
                    float* c = acc[mi][ni];
                    mma16816(c[0], c[1], c[2], c[3], ah0, ah1, ah2, ah3,
                             bh[ni][0], bh[ni][1]);
                    mma16816(c[0], c[1], c[2], c[3], ah0, ah1, ah2, ah3,
                             bl[ni][0], bl[ni][1]);
                    mma16816(c[0], c[1], c[2], c[3], al0, al1, al2, al3,
                             bh[ni][0], bh[ni][1]);
                }
            }
        }
    }

    // epilogue
    #pragma unroll
    for (int mi = 0; mi < 2; mi++) {
        #pragma unroll
        for (int ni = 0; ni < 4; ni++) {
            int col = col0 + wn * 32 + ni * 8 + tg * 2;
            float2 bz = *(const float2*)(bias + col);
            #pragma unroll
            for (int half = 0; half < 2; half++) {
                int row = row0 + wm * 32 + mi * 16 + gid + half * 8;
                float v0 = acc[mi][ni][half * 2 + 0] + bz.x;
                float v1 = acc[mi][ni][half * 2 + 1] + bz.y;
                size_t ob = (size_t)row * N + col;
                if (res) {
                    float2 r2 = *(const float2*)(res + ob);
                    v0 += r2.x; v1 += r2.y;
                }
                if (do_gelu) { v0 = gelu_f(v0); v1 = gelu_f(v1); }
                if (outf) {
                    *(float2*)(outf + ob) = make_float2(v0, v1);
                }
                if (ohi) {
                    __nv_bfloat16 h0 = __float2bfloat16(v0);
                    __nv_bfloat16 h1 = __float2bfloat16(v1);
                    __nv_bfloat16 l0 = __float2bfloat16(v0 - __bfloat162float(h0));
                    __nv_bfloat16 l1 = __float2bfloat16(v1 - __bfloat162float(h1));
                    *(uint32_t*)(ohi + ob) = (uint32_t)__bfloat16_as_ushort(h0) |
                                             ((uint32_t)__bfloat16_as_ushort(h1) << 16);
                    *(uint32_t*)(olo + ob) = (uint32_t)__bfloat16_as_ushort(l0) |
                                             ((uint32_t)__bfloat16_as_ushort(l1) << 16);
                }
            }
        }
    }
}

// ---------------- weight transpose + hi/lo split ----------------
__global__ void __launch_bounds__(256) wprep_kernel(
    const float* __restrict__ src, __nv_bfloat16* __restrict__ dhi,
    __nv_bfloat16* __restrict__ dlo, int K, int N)
{
    int i = blockIdx.x * 256 + threadIdx.x;
    if (i >= K * N) return;
    int k = i / N, n = i % N;
    float v = src[i];
    __nv_bfloat16 h = __float2bfloat16(v);
    dhi[n * K + k] = h;
    dlo[n * K + k] = __float2bfloat16(v - __bfloat162float(h));
}

// ---------------- LayerNorm -> bf16 hi/lo ----------------
__global__ void __launch_bounds__(256) ln_kernel(
    const float* __restrict__ x, const float* __restrict__ g,
    const float* __restrict__ b, __nv_bfloat16* __restrict__ ohi,
    __nv_bfloat16* __restrict__ olo)
{
    size_t row = blockIdx.x;
    int t = threadIdx.x;
    float v = x[row * CC + t];
    float s = v, s2 = v * v;
    #pragma unroll
    for (int o = 16; o > 0; o >>= 1) {
        s  += __shfl_xor_sync(0xffffffffu, s,  o);
        s2 += __shfl_xor_sync(0xffffffffu, s2, o);
    }
    __shared__ float ws[8], ws2[8];
    int w = t >> 5, l = t & 31;
    if (l == 0) { ws[w] = s; ws2[w] = s2; }
    __syncthreads();
    float sum = 0.f, sum2 = 0.f;
    #pragma unroll
    for (int i = 0; i < 8; i++) { sum += ws[i]; sum2 += ws2[i]; }
    float m   = sum * (1.0f / CC);
    float var = sum2 * (1.0f / CC) - m * m;
    float inv = rsqrtf(var + 1e-5f);
    float r = (v - m) * inv * g[t] + b[t];
    __nv_bfloat16 hb = __float2bfloat16(r);
    ohi[row * CC + t] = hb;
    olo[row * CC + t] = __float2bfloat16(r - __bfloat162float(hb));
}

// ---------------- slice softmax ----------------
__global__ void __launch_bounds__(128) slice_softmax_kernel(
    const float* __restrict__ xmid, const float* __restrict__ wsl,
    const float* __restrict__ bsl, const float* __restrict__ temp,
    float* __restrict__ sw)
{
    __shared__ float ws[32][64];
    int t = threadIdx.x;
    for (int i = t; i < DD * GG; i += 128) ws[i >> 6][i & 63] = wsl[i];
    __syncthreads();
    int warp = t >> 5, lane = t & 31;
    size_t task = (size_t)blockIdx.x * 4 + warp;
    int head = (int)(task & 7);
    size_t token = task >> 3;
    float x = xmid[token * CC + head * DD + lane];
    float l0 = bsl[lane], l1 = bsl[lane + 32];
    #pragma unroll
    for (int d = 0; d < 32; d++) {
        float xd = __shfl_sync(0xffffffffu, x, d);
        l0 += xd * ws[d][lane];
        l1 += xd * ws[d][lane + 32];
    }
    float it = 1.0f / temp[head];
    l0 *= it; l1 *= it;
    float mx = fmaxf(l0, l1);
    #pragma unroll
    for (int o = 16; o > 0; o >>= 1) mx = fmaxf(mx, __shfl_xor_sync(0xffffffffu, mx, o));
    float e0 = expf(l0 - mx), e1 = expf(l1 - mx);
    float sm = e0 + e1;
    #pragma unroll
    for (int o = 16; o > 0; o >>= 1) sm += __shfl_xor_sync(0xffffffffu, sm, o);
    float inv = 1.0f / sm;
    int b = (int)(token >> 15);
    int n = (int)(token & (NN - 1));
    size_t base = (((size_t)b * HH + head) * NN + n) * GG;
    sw[base + lane]      = e0 * inv;
    sw[base + 32 + lane] = e1 * inv;
}

// ---------------- zero accumulators ----------------
__global__ void zero_kernel() {
    int i = blockIdx.x * blockDim.x + threadIdx.x;
    if (i < BB * HH * GG * DD) g_tok[i] = 0.f;
    if (i < BB * HH * GG)      g_nrm[i] = 0.f;
}

// ---------------- slice_token accumulation ----------------
__global__ void __launch_bounds__(256) slice_token_kernel(
    const float* __restrict__ fxmid, const float* __restrict__ sw)
{
    const int CHN = 2048, NB = 32;
    int bh = blockIdx.y;
    int b = bh >> 3, h = bh & 7;
    int nbase = blockIdx.x * CHN;
    int t = threadIdx.x;
    int gp = t >> 3;
    int dq = t & 7;
    int d0 = dq * 4;
    __shared__ float sws[NB][64];
    __shared__ float fxs[NB][32];
    float a0[4] = {0, 0, 0, 0}, a1[4] = {0, 0, 0, 0};
    float n0 = 0.f, n1 = 0.f;
    size_t swbase = (size_t)bh * NN * GG;
    size_t fxbase = (size_t)b * NN * CC + h * DD;
    for (int nb = 0; nb < CHN; nb += NB) {
        __syncthreads();
        for (int i = t; i < NB * 16; i += 256) {
            int nn = i >> 4, c4 = (i & 15) * 4;
            *(float4*)&sws[nn][c4] =
                *(const float4*)&sw[swbase + (size_t)(nbase + nb + nn) * GG + c4];
        }
        for (int i = t; i < NB * 8; i += 256) {
            int nn = i >> 3, c4 = (i & 7) * 4;
            *(float4*)&fxs[nn][c4] =
                *(const float4*)&fxmid[fxbase + (size_t)(nbase + nb + nn) * CC + c4];
        }
        __syncthreads();
        #pragma unroll 4
        for (int nn = 0; nn < NB; nn++) {
            float s0 = sws[nn][gp], s1 = sws[nn][gp + 32];
            float4 f = *(const float4*)&fxs[nn][d0];
            a0[0] += s0 * f.x; a0[1] += s0 * f.y; a0[2] += s0 * f.z; a0[3] += s0 * f.w;
            a1[0] += s1 * f.x; a1[1] += s1 * f.y; a1[2] += s1 * f.z; a1[3] += s1 * f.w;
            if (dq == 0) { n0 += s0; n1 += s1; }
        }
    }
    size_t tb = (size_t)bh * GG * DD;
    #pragma unroll
    for (int j = 0; j < 4; j++) {
        atomicAdd(&g_tok[tb + gp * DD + d0 + j],        a0[j]);
        atomicAdd(&g_tok[tb + (gp + 32) * DD + d0 + j], a1[j]);
    }
    if (dq == 0) {
        atomicAdd(&g_nrm[bh * GG + gp],      n0);
        atomicAdd(&g_nrm[bh * GG + gp + 32], n1);
    }
}

// ---------------- tiny attention over G=64 slice tokens --------------------
__global__ void __launch_bounds__(64) attn_kernel(
    const float* __restrict__ wq, const float* __restrict__ wk,
    const float* __restrict__ wv)
{
    int bh = blockIdx.x;
    int g = threadIdx.x;
    __shared__ float st[64][33];
    __shared__ float ks2[64][33];
    __shared__ float vs[64][33];
    __shared__ float wqs[32][32], wks[32][32], wvs[32][32];
    for (int i = g; i < 1024; i += 64) {
        wqs[i >> 5][i & 31] = wq[i];
        wks[i >> 5][i & 31] = wk[i];
        wvs[i >> 5][i & 31] = wv[i];
    }
    float nv = g_nrm[bh * GG + g] + 1e-5f;
    float invn = 1.0f / nv;
    #pragma unroll
    for (int d = 0; d < 32; d++)
        st[g][d] = g_tok[((size_t)bh * GG + g) * DD + d] * invn;
    __syncthreads();
    float q[32];
    #pragma unroll 4
    for (int dout = 0; dout < 32; dout++) {
        float sq = 0.f, sk = 0.f, sv = 0.f;
        #pragma unroll
        for (int di = 0; di < 32; di++) {
            float s = st[g][di];
            sq += s * wqs[di][dout];
            sk += s * wks[di][dout];
            sv += s * wvs[di][dout];
        }
        q[dout] = sq; ks2[g][dout] = sk; vs[g][dout] = sv;
    }
    __syncthreads();
    float sc[64];
    float mx = -1e30f;
    const float scale = 0.17677669529663687f;
    #pragma unroll 4
    for (int kk = 0; kk < 64; kk++) {
        float s = 0.f;
        #pragma unroll
        for (int d = 0; d < 32; d++) s += q[d] * ks2[kk][d];
        s *= scale;
        sc[kk] = s;
        mx = fmaxf(mx, s);
    }
    float sum = 0.f;
    #pragma unroll 4
    for (int kk = 0; kk < 64; kk++) { sc[kk] = expf(sc[kk] - mx); sum += sc[kk]; }
    float inv = 1.0f / sum;
    #pragma unroll 4
    for (int d = 0; d < 32; d++) {
        float o = 0.f;
        #pragma unroll
        for (int kk = 0; kk < 64; kk++) o += sc[kk] * vs[kk][d];
        g_ot[((size_t)bh * GG + g) * DD + d] = o * inv;
    }
}

// ---------------- de-slice -> bf16 hi/lo ----------------
__global__ void __launch_bounds__(256) deslice_kernel(const float* __restrict__ sw)
{
    int bh = blockIdx.y;
    int b = bh >> 3, h = bh & 7;
    int nbase = blockIdx.x * 32;
    int t = threadIdx.x;
    int tt = t >> 3, dq = t & 7, d0 = dq * 4;
    __shared__ float ots[64][32];
    __shared__ float sws[32][64];
    for (int i = t; i < 512; i += 256) {
        int g = i >> 3, c4 = (i & 7) * 4;
        *(float4*)&ots[g][c4] = *(const float4*)&g_ot[((size_t)bh * GG + g) * DD + c4];
    }
    for (int i = t; i < 512; i += 256) {
        int nn = i >> 4, c4 = (i & 15) * 4;
        *(float4*)&sws[nn][c4] =
            *(const float4*)&sw[((size_t)bh * NN + nbase + nn) * GG + c4];
    }
    __syncthreads();
    float acc[4] = {0, 0, 0, 0};
    #pragma unroll 8
    for (int g = 0; g < 64; g++) {
        float s = sws[tt][g];
        float4 f = *(const float4*)&ots[g][d0];
        acc[0] += s * f.x; acc[1] += s * f.y; acc[2] += s * f.z; acc[3] += s * f.w;
    }
    size_t o = ((size_t)b * NN + nbase + tt) * CC + h * DD + d0;
    uint32_t ph[2], pl[2];
    #pragma unroll
    for (int hw = 0; hw < 2; hw++) {
        float x0 = acc[hw * 2], x1 = acc[hw * 2 + 1];
        __nv_bfloat16 h0 = __float2bfloat16(x0), h1 = __float2bfloat16(x1);
        __nv_bfloat16 l0 = __float2bfloat16(x0 - __bfloat162float(h0));
        __nv_bfloat16 l1 = __float2bfloat16(x1 - __bfloat162float(h1));
        ph[hw] = (uint32_t)__bfloat16_as_ushort(h0) | ((uint32_t)__bfloat16_as_ushort(h1) << 16);
        pl[hw] = (uint32_t)__bfloat16_as_ushort(l0) | ((uint32_t)__bfloat16_as_ushort(l1) << 16);
    }
    *(uint2*)(g_ox_hi + o) = make_uint2(ph[0], ph[1]);
    *(uint2*)(g_ox_lo + o) = make_uint2(pl[0], pl[1]);
}

// ---------------- launch ----------------
extern "C" void kernel_launch(void* const* d_in, const int* in_sizes, int n_in,
                              void* d_out, int out_size)
{
    const float* fx     = (const float*)d_in[0];
    const float* ln1_g  = (const float*)d_in[1];
    const float* ln1_b  = (const float*)d_in[2];
    const float* w_fx   = (const float*)d_in[3];
    const float* b_fx   = (const float*)d_in[4];
    const float* w_x    = (const float*)d_in[5];
    const float* b_x    = (const float*)d_in[6];
    const float* w_sl   = (const float*)d_in[7];
    const float* b_sl   = (const float*)d_in[8];
    const float* temp   = (const float*)d_in[9];
    const float* w_q    = (const float*)d_in[10];
    const float* w_k    = (const float*)d_in[11];
    const float* w_v    = (const float*)d_in[12];
    const float* w_o    = (const float*)d_in[13];
    const float* b_o    = (const float*)d_in[14];
    const float* ln2_g  = (const float*)d_in[15];
    const float* ln2_b  = (const float*)d_in[16];
    const float* w1     = (const float*)d_in[17];
    const float* b1     = (const float*)d_in[18];
    const float* w2     = (const float*)d_in[19];
    const float* b2     = (const float*)d_in[20];
    float* out = (float*)d_out;

    __nv_bfloat16 *p_h_hi, *p_h_lo, *p_ox_hi, *p_ox_lo, *p_hid_hi, *p_hid_lo, *p_wt_hi, *p_wt_lo;
    float *p_fxmid, *p_xmid, *p_sw, *p_fx2;
    cudaGetSymbolAddress((void**)&p_h_hi,   g_h_hi);
    cudaGetSymbolAddress((void**)&p_h_lo,   g_h_lo);
    cudaGetSymbolAddress((void**)&p_ox_hi,  g_ox_hi);
    cudaGetSymbolAddress((void**)&p_ox_lo,  g_ox_lo);
    cudaGetSymbolAddress((void**)&p_hid_hi, g_hid_hi);
    cudaGetSymbolAddress((void**)&p_hid_lo, g_hid_lo);
    cudaGetSymbolAddress((void**)&p_wt_hi,  g_wt_hi);
    cudaGetSymbolAddress((void**)&p_wt_lo,  g_wt_lo);
    cudaGetSymbolAddress((void**)&p_fxmid,  g_fxmid);
    cudaGetSymbolAddress((void**)&p_xmid,   g_xmid);
    cudaGetSymbolAddress((void**)&p_sw,     g_sw);
    cudaGetSymbolAddress((void**)&p_fx2,    g_fx2);

    // weight prep (transpose + hi/lo split)
    wprep_kernel<<<(CC * CC + 255) / 256, 256>>>(w_fx, p_wt_hi + WFX_OFF, p_wt_lo + WFX_OFF, CC, CC);
    wprep_kernel<<<(CC * CC + 255) / 256, 256>>>(w_x,  p_wt_hi + WX_OFF,  p_wt_lo + WX_OFF,  CC, CC);
    wprep_kernel<<<(CC * CC + 255) / 256, 256>>>(w_o,  p_wt_hi + WO_OFF,  p_wt_lo + WO_OFF,  CC, CC);
    wprep_kernel<<<(CC * HID + 255) / 256, 256>>>(w1,  p_wt_hi + W1_OFF,  p_wt_lo + W1_OFF,  CC, HID);
    wprep_kernel<<<(HID * CC + 255) / 256, 256>>>(w2,  p_wt_hi + W2_OFF,  p_wt_lo + W2_OFF,  HID, CC);

    // 1. LN1 -> h hi/lo
    ln_kernel<<<BN, 256>>>(fx, ln1_g, ln1_b, p_h_hi, p_h_lo);
    // 2. fx_mid = h @ w_fx + b_fx  (f32 out)
    hmma_gemm<<<dim3(CC / 128, BN / 128), 512>>>(
        p_h_hi, p_h_lo, p_wt_hi + WFX_OFF, p_wt_lo + WFX_OFF,
        b_fx, nullptr, p_fxmid, nullptr, nullptr, CC, CC, 0);
    // 3. x_mid = h @ w_x + b_x  (f32 out)
    hmma_gemm<<<dim3(CC / 128, BN / 128), 512>>>(
        p_h_hi, p_h_lo, p_wt_hi + WX_OFF, p_wt_lo + WX_OFF,
        b_x, nullptr, p_xmid, nullptr, nullptr, CC, CC, 0);
    // 4. zero slice accumulators
    zero_kernel<<<(BB * HH * GG * DD + 255) / 256, 256>>>();
    // 5. slice softmax
    slice_softmax_kernel<<<(BN * HH) / 4, 128>>>(p_xmid, w_sl, b_sl, temp, p_sw);
    // 6. slice token accumulation
    slice_token_kernel<<<dim3(NN / 2048, BB * HH), 256>>>(p_fxmid, p_sw);
    // 7. tiny attention over slice tokens
    attn_kernel<<<BB * HH, 64>>>(w_q, w_k, w_v);
    // 8. de-slice -> out_x hi/lo
    deslice_kernel<<<dim3(NN / 32, BB * HH), 256>>>(p_sw);
    // 9. fx2 = out_x @ w_o + b_o + fx  (f32 out)
    hmma_gemm<<<dim3(CC / 128, BN / 128), 512>>>(
        p_ox_hi, p_ox_lo, p_wt_hi + WO_OFF, p_wt_lo + WO_OFF,
        b_o, fx, p_fx2, nullptr, nullptr, CC, CC, 0);
    // 10. LN2 -> h hi/lo (reuse buffers)
    ln_kernel<<<BN, 256>>>(p_fx2, ln2_g, ln2_b, p_h_hi, p_h_lo);
    // 11. hid = gelu(h2 @ w1 + b1) -> bf16 hi/lo
    hmma_gemm<<<dim3(HID / 128, BN / 128), 512>>>(
        p_h_hi, p_h_lo, p_wt_hi + W1_OFF, p_wt_lo + W1_OFF,
        b1, nullptr, nullptr, p_hid_hi, p_hid_lo, HID, CC, 1);
    // 12. out = hid @ w2 + b2 + fx2  (f32 out)
    hmma_gemm<<<dim3(CC / 128, BN / 128), 512>>>(
        p_hid_hi, p_hid_lo, p_wt_hi + W2_OFF, p_wt_lo + W2_OFF,
        b2, p_fx2, out, nullptr, nullptr, CC, HID, 0);
}

// round 5
// speedup vs baseline: 2.0716x; 1.3274x over previous
#include <cuda_runtime.h>
#include <cuda_bf16.h>
#include <math.h>
#include <stdint.h>

// ---------------- problem constants ----------------
#define BB 4
#define NN 32768
#define CC 256
#define HH 8
#define DD 32
#define GG 64
#define HID 1024
#define BN (BB * NN)          // 131072 tokens

// ---------------- scratch (device globals) ----------------
__device__ __nv_bfloat16 g_h_hi[(size_t)BN * CC];
__device__ __nv_bfloat16 g_h_lo[(size_t)BN * CC];
__device__ float g_fxmid[(size_t)BN * CC];
__device__ float g_xmid[(size_t)BN * CC];
__device__ float g_sw[(size_t)BN * HH * GG];
__device__ __nv_bfloat16 g_ox_hi[(size_t)BN * CC];
__device__ __nv_bfloat16 g_ox_lo[(size_t)BN * CC];
__device__ float g_fx2[(size_t)BN * CC];
__device__ __nv_bfloat16 g_hid_hi[(size_t)BN * HID];
__device__ __nv_bfloat16 g_hid_lo[(size_t)BN * HID];
__device__ float g_tok[BB * HH * GG * DD];
__device__ float g_nrm[BB * HH * GG];
__device__ float g_ot[BB * HH * GG * DD];
// transposed bf16 hi/lo weights, [N,K] row-major, concatenated
#define WFX_OFF 0
#define WX_OFF  65536
#define WO_OFF  131072
#define W1_OFF  196608
#define W2_OFF  458752
#define WT_TOTAL 720896
__device__ __nv_bfloat16 g_wt_hi[WT_TOTAL];
__device__ __nv_bfloat16 g_wt_lo[WT_TOTAL];

__device__ __forceinline__ float gelu_f(float x) {
    return 0.5f * x * (1.0f + erff(x * 0.70710678118654752f));
}
__device__ __forceinline__ uint32_t s2u(const void* p) {
    uint32_t a;
    asm("{ .reg .u64 t; cvta.to.shared.u64 t, %1; cvt.u32.u64 %0, t; }" : "=r"(a) : "l"(p));
    return a;
}
__device__ __forceinline__ uint32_t sw128(uint32_t b) { return b ^ ((b >> 3) & 0x70); }

#define CPA16(dst, src) \
    asm volatile("cp.async.cg.shared.global [%0], [%1], 16;" :: "r"(dst), "l"(src))
#define CPA_COMMIT() asm volatile("cp.async.commit_group;" ::: "memory")
template <int N_>
__device__ __forceinline__ void cpa_wait() {
    asm volatile("cp.async.wait_group %0;" :: "n"(N_) : "memory");
}
#define LDSM4(r0, r1, r2, r3, addr) \
    asm volatile("ldmatrix.sync.aligned.m8n8.x4.shared.b16 {%0,%1,%2,%3}, [%4];" \
        : "=r"(r0), "=r"(r1), "=r"(r2), "=r"(r3) : "r"(addr))

__device__ __forceinline__ void mma16816(
    float& c0, float& c1, float& c2, float& c3,
    uint32_t a0, uint32_t a1, uint32_t a2, uint32_t a3,
    uint32_t b0, uint32_t b1)
{
    asm volatile(
        "mma.sync.aligned.m16n8k16.row.col.f32.bf16.bf16.f32 "
        "{%0,%1,%2,%3}, {%4,%5,%6,%7}, {%8,%9}, {%0,%1,%2,%3};"
        : "+f"(c0), "+f"(c1), "+f"(c2), "+f"(c3)
        : "r"(a0), "r"(a1), "r"(a2), "r"(a3), "r"(b0), "r"(b1));
}

// ---------------- HMMA hi/lo GEMM, ldmatrix + cp.async double buffer -------
// C[M,N] = A[M,K] @ B[N,K]^T (+bias)(+res)(gelu)
// Block 128x128, 512 threads (16 warps 4x4), warp tile 32x32, KC=64.
// SMEM per stage: Ah,Al,Bh,Bl each 128x64 bf16 SW128 (16KB) = 64KB; 2 stages.
#define KC 64
#define TILE_B 16384
#define STAGE_B 65536
#define SMEM_TOT 131072

// offsets within stage
#define OAH 0
#define OAL 16384
#define OBH 32768
#define OBL 49152

__device__ __forceinline__ void load_stage(
    const __nv_bfloat16* __restrict__ Ahi, const __nv_bfloat16* __restrict__ Alo,
    const __nv_bfloat16* __restrict__ Bhi, const __nv_bfloat16* __restrict__ Blo,
    uint32_t sbase, int row0, int col0, int k0, int K, int t)
{
    #pragma unroll
    for (int i = 0; i < 2; i++) {
        int id = t + i * 512;
        int r = id >> 3, c16 = id & 7;
        uint32_t so = sw128((uint32_t)(r * 128 + c16 * 16));
        size_t ga = (size_t)(row0 + r) * K + k0 + c16 * 8;
        size_t gb = (size_t)(col0 + r) * K + k0 + c16 * 8;
        CPA16(sbase + OAH + so, Ahi + ga);
        CPA16(sbase + OAL + so, Alo + ga);
        CPA16(sbase + OBH + so, Bhi + gb);
        CPA16(sbase + OBL + so, Blo + gb);
    }
}

__global__ void __launch_bounds__(512) hmma_gemm(
    const __nv_bfloat16* __restrict__ Ahi, const __nv_bfloat16* __restrict__ Alo,
    const __nv_bfloat16* __restrict__ Bhi, const __nv_bfloat16* __restrict__ Blo,
    const float* __restrict__ bias, const float* __restrict__ bias2,
    const float* __restrict__ res,
    float* __restrict__ outf, float* __restrict__ outf2,
    __nv_bfloat16* __restrict__ ohi, __nv_bfloat16* __restrict__ olo,
    int N, int K, int ostride, int do_gelu)
{
    extern __shared__ char smem[];
    uint32_t sb = s2u(smem);
    int t = threadIdx.x, lane = t & 31, wid = t >> 5;
    int wm = wid & 3, wn = wid >> 2;
    int row0 = blockIdx.y * 128, col0 = blockIdx.x * 128;

    // fused dual-output routing (projection GEMM): cols >= 256 -> outf2/bias2
    int outcol0 = col0;
    if (outf2 && col0 >= 256) { outf = outf2; bias = bias2; outcol0 = col0 - 256; }

    float acc[2][4][4];
    #pragma unroll
    for (int mi = 0; mi < 2; mi++)
        #pragma unroll
        for (int ni = 0; ni < 4; ni++)
            #pragma unroll
            for (int j = 0; j < 4; j++) acc[mi][ni][j] = 0.f;

    // per-lane ldmatrix source coordinates
    int a_r = (lane & 7) + ((lane >> 3) & 1) * 8;   // row within 16-row tile
    int a_kb = (lane >> 4) * 16;                    // byte within 32B k-span
    int b_r = (lane & 7) + ((lane >> 4) & 1) * 8;
    int b_kb = ((lane >> 3) & 1) * 16;

    int chunks = K >> 6;
    load_stage(Ahi, Alo, Bhi, Blo, sb, row0, col0, 0, K, t);
    CPA_COMMIT();

    for (int c = 0; c < chunks; c++) {
        if (c + 1 < chunks) {
            load_stage(Ahi, Alo, Bhi, Blo, sb + ((c + 1) & 1) * STAGE_B,
                       row0, col0, (c + 1) * KC, K, t);
            CPA_COMMIT();
            cpa_wait<1>();
        } else {
            cpa_wait<0>();
        }
        __syncthreads();
        uint32_t st = sb + (c & 1) * STAGE_B;

        #pragma unroll
        for (int ks = 0; ks < 4; ks++) {
            uint32_t ah[2][4], al[2][4], bh[4][2], bl[4][2];
            #pragma unroll
            for (int mi = 0; mi < 2; mi++) {
                int rr = wm * 32 + mi * 16 + a_r;
                uint32_t off = sw128((uint32_t)(rr * 128 + ks * 32 + a_kb));
                LDSM4(ah[mi][0], ah[mi][1], ah[mi][2], ah[mi][3], st + OAH + off);
                LDSM4(al[mi][0], al[mi][1], al[mi][2], al[mi][3], st + OAL + off);
            }
            #pragma unroll
            for (int np = 0; np < 2; np++) {
                int rr = wn * 32 + np * 16 + b_r;
                uint32_t off = sw128((uint32_t)(rr * 128 + ks * 32 + b_kb));
                uint32_t r0, r1, r2, r3;
                LDSM4(r0, r1, r2, r3, st + OBH + off);
                bh[np * 2][0] = r0; bh[np * 2][1] = r1;
                bh[np * 2 + 1][0] = r2; bh[np * 2 + 1][1] = r3;
                LDSM4(r0, r1, r2, r3, st + OBL + off);
                bl[np * 2][0] = r0; bl[np * 2][1] = r1;
                bl[np * 2 + 1][0] = r2; bl[np * 2 + 1][1] = r3;
            }
            #pragma unroll
            for (int mi = 0; mi < 2; mi++) {
                #pragma unroll
                for (int ni = 0; ni < 4; ni++) {
                    float* cc = acc[mi][ni];
                    mma16816(cc[0], cc[1], cc[2], cc[3],
                             ah[mi][0], ah[mi][1], ah[mi][2], ah[mi][3],
                             bh[ni][0], bh[ni][1]);
                    mma16816(cc[0], cc[1], cc[2], cc[3],
                             ah[mi][0], ah[mi][1], ah[mi][2], ah[mi][3],
                             bl[ni][0], bl[ni][1]);
                    mma16816(cc[0], cc[1], cc[2], cc[3],
                             al[mi][0], al[mi][1], al[mi][2], al[mi][3],
                             bh[ni][0], bh[ni][1]);
                }
            }
        }
        __syncthreads();
    }

    // epilogue
    int gid = lane >> 2, tg = lane & 3;
    #pragma unroll
    for (int mi = 0; mi < 2; mi++) {
        #pragma unroll
        for (int ni = 0; ni < 4; ni++) {
            int col = outcol0 + wn * 32 + ni * 8 + tg * 2;
            float2 bz = *(const float2*)(bias + col);
            #pragma unroll
            for (int half = 0; half < 2; half++) {
                int row = row0 + wm * 32 + mi * 16 + gid + half * 8;
                float v0 = acc[mi][ni][half * 2 + 0] + bz.x;
                float v1 = acc[mi][ni][half * 2 + 1] + bz.y;
                size_t ob = (size_t)row * ostride + col;
                if (res) {
                    float2 r2 = *(const float2*)(res + ob);
                    v0 += r2.x; v1 += r2.y;
                }
                if (do_gelu) { v0 = gelu_f(v0); v1 = gelu_f(v1); }
                if (outf) {
                    *(float2*)(outf + ob) = make_float2(v0, v1);
                }
                if (ohi) {
                    __nv_bfloat16 h0 = __float2bfloat16(v0);
                    __nv_bfloat16 h1 = __float2bfloat16(v1);
                    __nv_bfloat16 l0 = __float2bfloat16(v0 - __bfloat162float(h0));
                    __nv_bfloat16 l1 = __float2bfloat16(v1 - __bfloat162float(h1));
                    *(uint32_t*)(ohi + ob) = (uint32_t)__bfloat16_as_ushort(h0) |
                                             ((uint32_t)__bfloat16_as_ushort(h1) << 16);
                    *(uint32_t*)(olo + ob) = (uint32_t)__bfloat16_as_ushort(l0) |
                                             ((uint32_t)__bfloat16_as_ushort(l1) << 16);
                }
            }
        }
    }
}

// ---------------- weight transpose + hi/lo split ----------------
__global__ void __launch_bounds__(256) wprep_kernel(
    const float* __restrict__ src, __nv_bfloat16* __restrict__ dhi,
    __nv_bfloat16* __restrict__ dlo, int K, int N)
{
    int i = blockIdx.x * 256 + threadIdx.x;
    if (i >= K * N) return;
    int k = i / N, n = i % N;
    float v = src[i];
    __nv_bfloat16 h = __float2bfloat16(v);
    dhi[n * K + k] = h;
    dlo[n * K + k] = __float2bfloat16(v - __bfloat162float(h));
}

// ---------------- LayerNorm -> bf16 hi/lo ----------------
__global__ void __launch_bounds__(256) ln_kernel(
    const float* __restrict__ x, const float* __restrict__ g,
    const float* __restrict__ b, __nv_bfloat16* __restrict__ ohi,
    __nv_bfloat16* __restrict__ olo)
{
    size_t row = blockIdx.x;
    int t = threadIdx.x;
    float v = x[row * CC + t];
    float s = v, s2 = v * v;
    #pragma unroll
    for (int o = 16; o > 0; o >>= 1) {
        s  += __shfl_xor_sync(0xffffffffu, s,  o);
        s2 += __shfl_xor_sync(0xffffffffu, s2, o);
    }
    __shared__ float ws[8], ws2[8];
    int w = t >> 5, l = t & 31;
    if (l == 0) { ws[w] = s; ws2[w] = s2; }
    __syncthreads();
    float sum = 0.f, sum2 = 0.f;
    #pragma unroll
    for (int i = 0; i < 8; i++) { sum += ws[i]; sum2 += ws2[i]; }
    float m   = sum * (1.0f / CC);
    float var = sum2 * (1.0f / CC) - m * m;
    float inv = rsqrtf(var + 1e-5f);
    float r = (v - m) * inv * g[t] + b[t];
    __nv_bfloat16 hb = __float2bfloat16(r);
    ohi[row * CC + t] = hb;
    olo[row * CC + t] = __float2bfloat16(r - __bfloat162float(hb));
}

// ---------------- slice softmax ----------------
__global__ void __launch_bounds__(128) slice_softmax_kernel(
    const float* __restrict__ xmid, const float* __restrict__ wsl,
    const float* __restrict__ bsl, const float* __restrict__ temp,
    float* __restrict__ sw)
{
    __shared__ float ws[32][64];
    int t = threadIdx.x;
    for (int i = t; i < DD * GG; i += 128) ws[i >> 6][i & 63] = wsl[i];
    __syncthreads();
    int warp = t >> 5, lane = t & 31;
    size_t task = (size_t)blockIdx.x * 4 + warp;
    int head = (int)(task & 7);
    size_t token = task >> 3;
    float x = xmid[token * CC + head * DD + lane];
    float l0 = bsl[lane], l1 = bsl[lane + 32];
    #pragma unroll
    for (int d = 0; d < 32; d++) {
        float xd = __shfl_sync(0xffffffffu, x, d);
        l0 += xd * ws[d][lane];
        l1 += xd * ws[d][lane + 32];
    }
    float it = 1.0f / temp[head];
    l0 *= it; l1 *= it;
    float mx = fmaxf(l0, l1);
    #pragma unroll
    for (int o = 16; o > 0; o >>= 1) mx = fmaxf(mx, __shfl_xor_sync(0xffffffffu, mx, o));
    float e0 = expf(l0 - mx), e1 = expf(l1 - mx);
    float sm = e0 + e1;
    #pragma unroll
    for (int o = 16; o > 0; o >>= 1) sm += __shfl_xor_sync(0xffffffffu, sm, o);
    float inv = 1.0f / sm;
    int b = (int)(token >> 15);
    int n = (int)(token & (NN - 1));
    size_t base = (((size_t)b * HH + head) * NN + n) * GG;
    sw[base + lane]      = e0 * inv;
    sw[base + 32 + lane] = e1 * inv;
}

// ---------------- zero accumulators ----------------
__global__ void zero_kernel() {
    int i = blockIdx.x * blockDim.x + threadIdx.x;
    if (i < BB * HH * GG * DD) g_tok[i] = 0.f;
    if (i < BB * HH * GG)      g_nrm[i] = 0.f;
}

// ---------------- slice_token accumulation ----------------
__global__ void __launch_bounds__(256) slice_token_kernel(
    const float* __restrict__ fxmid, const float* __restrict__ sw)
{
    const int CHN = 2048, NB = 32;
    int bh = blockIdx.y;
    int b = bh >> 3, h = bh & 7;
    int nbase = blockIdx.x * CHN;
    int t = threadIdx.x;
    int gp = t >> 3;
    int dq = t & 7;
    int d0 = dq * 4;
    __shared__ float sws[NB][64];
    __shared__ float fxs[NB][32];
    float a0[4] = {0, 0, 0, 0}, a1[4] = {0, 0, 0, 0};
    float n0 = 0.f, n1 = 0.f;
    size_t swbase = (size_t)bh * NN * GG;
    size_t fxbase = (size_t)b * NN * CC + h * DD;
    for (int nb = 0; nb < CHN; nb += NB) {
        __syncthreads();
        for (int i = t; i < NB * 16; i += 256) {
            int nn = i >> 4, c4 = (i & 15) * 4;
            *(float4*)&sws[nn][c4] =
                *(const float4*)&sw[swbase + (size_t)(nbase + nb + nn) * GG + c4];
        }
        for (int i = t; i < NB * 8; i += 256) {
            int nn = i >> 3, c4 = (i & 7) * 4;
            *(float4*)&fxs[nn][c4] =
                *(const float4*)&fxmid[fxbase + (size_t)(nbase + nb + nn) * CC + c4];
        }
        __syncthreads();
        #pragma unroll 4
        for (int nn = 0; nn < NB; nn++) {
            float s0 = sws[nn][gp], s1 = sws[nn][gp + 32];
            float4 f = *(const float4*)&fxs[nn][d0];
            a0[0] += s0 * f.x; a0[1] += s0 * f.y; a0[2] += s0 * f.z; a0[3] += s0 * f.w;
            a1[0] += s1 * f.x; a1[1] += s1 * f.y; a1[2] += s1 * f.z; a1[3] += s1 * f.w;
            if (dq == 0) { n0 += s0; n1 += s1; }
        }
    }
    size_t tb = (size_t)bh * GG * DD;
    #pragma unroll
    for (int j = 0; j < 4; j++) {
        atomicAdd(&g_tok[tb + gp * DD + d0 + j],        a0[j]);
        atomicAdd(&g_tok[tb + (gp + 32) * DD + d0 + j], a1[j]);
    }
    if (dq == 0) {
        atomicAdd(&g_nrm[bh * GG + gp],      n0);
        atomicAdd(&g_nrm[bh * GG + gp + 32], n1);
    }
}

// ---------------- tiny attention over G=64 slice tokens --------------------
__global__ void __launch_bounds__(64) attn_kernel(
    const float* __restrict__ wq, const float* __restrict__ wk,
    const float* __restrict__ wv)
{
    int bh = blockIdx.x;
    int g = threadIdx.x;
    __shared__ float st[64][33];
    __shared__ float ks2[64][33];
    __shared__ float vs[64][33];
    __shared__ float wqs[32][32], wks[32][32], wvs[32][32];
    for (int i = g; i < 1024; i += 64) {
        wqs[i >> 5][i & 31] = wq[i];
        wks[i >> 5][i & 31] = wk[i];
        wvs[i >> 5][i & 31] = wv[i];
    }
    float nv = g_nrm[bh * GG + g] + 1e-5f;
    float invn = 1.0f / nv;
    #pragma unroll
    for (int d = 0; d < 32; d++)
        st[g][d] = g_tok[((size_t)bh * GG + g) * DD + d] * invn;
    __syncthreads();
    float q[32];
    #pragma unroll 4
    for (int dout = 0; dout < 32; dout++) {
        float sq = 0.f, sk = 0.f, sv = 0.f;
        #pragma unroll
        for (int di = 0; di < 32; di++) {
            float s = st[g][di];
            sq += s * wqs[di][dout];
            sk += s * wks[di][dout];
            sv += s * wvs[di][dout];
        }
        q[dout] = sq; ks2[g][dout] = sk; vs[g][dout] = sv;
    }
    __syncthreads();
    float sc[64];
    float mx = -1e30f;
    const float scale = 0.17677669529663687f;
    #pragma unroll 4
    for (int kk = 0; kk < 64; kk++) {
        float s = 0.f;
        #pragma unroll
        for (int d = 0; d < 32; d++) s += q[d] * ks2[kk][d];
        s *= scale;
        sc[kk] = s;
        mx = fmaxf(mx, s);
    }
    float sum = 0.f;
    #pragma unroll 4
    for (int kk = 0; kk < 64; kk++) { sc[kk] = expf(sc[kk] - mx); sum += sc[kk]; }
    float inv = 1.0f / sum;
    #pragma unroll 4
    for (int d = 0; d < 32; d++) {
        float o = 0.f;
        #pragma unroll
        for (int kk = 0; kk < 64; kk++) o += sc[kk] * vs[kk][d];
        g_ot[((size_t)bh * GG + g) * DD + d] = o * inv;
    }
}

// ---------------- de-slice -> bf16 hi/lo ----------------
__global__ void __launch_bounds__(256) deslice_kernel(const float* __restrict__ sw)
{
    int bh = blockIdx.y;
    int b = bh >> 3, h = bh & 7;
    int nbase = blockIdx.x * 32;
    int t = threadIdx.x;
    int tt = t >> 3, dq = t & 7, d0 = dq * 4;
    __shared__ float ots[64][32];
    __shared__ float sws[32][64];
    for (int i = t; i < 512; i += 256) {
        int g = i >> 3, c4 = (i & 7) * 4;
        *(float4*)&ots[g][c4] = *(const float4*)&g_ot[((size_t)bh * GG + g) * DD + c4];
    }
    for (int i = t; i < 512; i += 256) {
        int nn = i >> 4, c4 = (i & 15) * 4;
        *(float4*)&sws[nn][c4] =
            *(const float4*)&sw[((size_t)bh * NN + nbase + nn) * GG + c4];
    }
    __syncthreads();
    float acc[4] = {0, 0, 0, 0};
    #pragma unroll 8
    for (int g = 0; g < 64; g++) {
        float s = sws[tt][g];
        float4 f = *(const float4*)&ots[g][d0];
        acc[0] += s * f.x; acc[1] += s * f.y; acc[2] += s * f.z; acc[3] += s * f.w;
    }
    size_t o = ((size_t)b * NN + nbase + tt) * CC + h * DD + d0;
    uint32_t ph[2], pl[2];
    #pragma unroll
    for (int hw = 0; hw < 2; hw++) {
        float x0 = acc[hw * 2], x1 = acc[hw * 2 + 1];
        __nv_bfloat16 h0 = __float2bfloat16(x0), h1 = __float2bfloat16(x1);
        __nv_bfloat16 l0 = __float2bfloat16(x0 - __bfloat162float(h0));
        __nv_bfloat16 l1 = __float2bfloat16(x1 - __bfloat162float(h1));
        ph[hw] = (uint32_t)__bfloat16_as_ushort(h0) | ((uint32_t)__bfloat16_as_ushort(h1) << 16);
        pl[hw] = (uint32_t)__bfloat16_as_ushort(l0) | ((uint32_t)__bfloat16_as_ushort(l1) << 16);
    }
    *(uint2*)(g_ox_hi + o) = make_uint2(ph[0], ph[1]);
    *(uint2*)(g_ox_lo + o) = make_uint2(pl[0], pl[1]);
}

// ---------------- launch ----------------
extern "C" void kernel_launch(void* const* d_in, const int* in_sizes, int n_in,
                              void* d_out, int out_size)
{
    const float* fx     = (const float*)d_in[0];
    const float* ln1_g  = (const float*)d_in[1];
    const float* ln1_b  = (const float*)d_in[2];
    const float* w_fx   = (const float*)d_in[3];
    const float* b_fx   = (const float*)d_in[4];
    const float* w_x    = (const float*)d_in[5];
    const float* b_x    = (const float*)d_in[6];
    const float* w_sl   = (const float*)d_in[7];
    const float* b_sl   = (const float*)d_in[8];
    const float* temp   = (const float*)d_in[9];
    const float* w_q    = (const float*)d_in[10];
    const float* w_k    = (const float*)d_in[11];
    const float* w_v    = (const float*)d_in[12];
    const float* w_o    = (const float*)d_in[13];
    const float* b_o    = (const float*)d_in[14];
    const float* ln2_g  = (const float*)d_in[15];
    const float* ln2_b  = (const float*)d_in[16];
    const float* w1     = (const float*)d_in[17];
    const float* b1     = (const float*)d_in[18];
    const float* w2     = (const float*)d_in[19];
    const float* b2     = (const float*)d_in[20];
    float* out = (float*)d_out;

    __nv_bfloat16 *p_h_hi, *p_h_lo, *p_ox_hi, *p_ox_lo, *p_hid_hi, *p_hid_lo, *p_wt_hi, *p_wt_lo;
    float *p_fxmid, *p_xmid, *p_sw, *p_fx2;
    cudaGetSymbolAddress((void**)&p_h_hi,   g_h_hi);
    cudaGetSymbolAddress((void**)&p_h_lo,   g_h_lo);
    cudaGetSymbolAddress((void**)&p_ox_hi,  g_ox_hi);
    cudaGetSymbolAddress((void**)&p_ox_lo,  g_ox_lo);
    cudaGetSymbolAddress((void**)&p_hid_hi, g_hid_hi);
    cudaGetSymbolAddress((void**)&p_hid_lo, g_hid_lo);
    cudaGetSymbolAddress((void**)&p_wt_hi,  g_wt_hi);
    cudaGetSymbolAddress((void**)&p_wt_lo,  g_wt_lo);
    cudaGetSymbolAddress((void**)&p_fxmid,  g_fxmid);
    cudaGetSymbolAddress((void**)&p_xmid,   g_xmid);
    cudaGetSymbolAddress((void**)&p_sw,     g_sw);
    cudaGetSymbolAddress((void**)&p_fx2,    g_fx2);

    cudaFuncSetAttribute(hmma_gemm, cudaFuncAttributeMaxDynamicSharedMemorySize, SMEM_TOT);

    // weight prep (transpose + hi/lo split)
    wprep_kernel<<<(CC * CC + 255) / 256, 256>>>(w_fx, p_wt_hi + WFX_OFF, p_wt_lo + WFX_OFF, CC, CC);
    wprep_kernel<<<(CC * CC + 255) / 256, 256>>>(w_x,  p_wt_hi + WX_OFF,  p_wt_lo + WX_OFF,  CC, CC);
    wprep_kernel<<<(CC * CC + 255) / 256, 256>>>(w_o,  p_wt_hi + WO_OFF,  p_wt_lo + WO_OFF,  CC, CC);
    wprep_kernel<<<(CC * HID + 255) / 256, 256>>>(w1,  p_wt_hi + W1_OFF,  p_wt_lo + W1_OFF,  CC, HID);
    wprep_kernel<<<(HID * CC + 255) / 256, 256>>>(w2,  p_wt_hi + W2_OFF,  p_wt_lo + W2_OFF,  HID, CC);

    // 1. LN1 -> h hi/lo
    ln_kernel<<<BN, 256>>>(fx, ln1_g, ln1_b, p_h_hi, p_h_lo);
    // 2+3. fused projections: [fx_mid | x_mid] = h @ [w_fx | w_x] (N=512)
    hmma_gemm<<<dim3(4, BN / 128), 512, SMEM_TOT>>>(
        p_h_hi, p_h_lo, p_wt_hi + WFX_OFF, p_wt_lo + WFX_OFF,
        b_fx, b_x, nullptr, p_fxmid, p_xmid, nullptr, nullptr, 512, CC, CC, 0);
    // 4. zero slice accumulators
    zero_kernel<<<(BB * HH * GG * DD + 255) / 256, 256>>>();
    // 5. slice softmax
    slice_softmax_kernel<<<(BN * HH) / 4, 128>>>(p_xmid, w_sl, b_sl, temp, p_sw);
    // 6. slice token accumulation
    slice_token_kernel<<<dim3(NN / 2048, BB * HH), 256>>>(p_fxmid, p_sw);
    // 7. tiny attention over slice tokens
    attn_kernel<<<BB * HH, 64>>>(w_q, w_k, w_v);
    // 8. de-slice -> out_x hi/lo
    deslice_kernel<<<dim3(NN / 32, BB * HH), 256>>>(p_sw);
    // 9. fx2 = out_x @ w_o + b_o + fx
    hmma_gemm<<<dim3(2, BN / 128), 512, SMEM_TOT>>>(
        p_ox_hi, p_ox_lo, p_wt_hi + WO_OFF, p_wt_lo + WO_OFF,
        b_o, nullptr, fx, p_fx2, nullptr, nullptr, nullptr, CC, CC, CC, 0);
    // 10. LN2 -> h hi/lo (reuse buffers)
    ln_kernel<<<BN, 256>>>(p_fx2, ln2_g, ln2_b, p_h_hi, p_h_lo);
    // 11. hid = gelu(h2 @ w1 + b1) -> bf16 hi/lo
    hmma_gemm<<<dim3(8, BN / 128), 512, SMEM_TOT>>>(
        p_h_hi, p_h_lo, p_wt_hi + W1_OFF, p_wt_lo + W1_OFF,
        b1, nullptr, nullptr, nullptr, nullptr, p_hid_hi, p_hid_lo, HID, CC, HID, 1);
    // 12. out = hid @ w2 + b2 + fx2
    hmma_gemm<<<dim3(2, BN / 128), 512, SMEM_TOT>>>(
        p_hid_hi, p_hid_lo, p_wt_hi + W2_OFF, p_wt_lo + W2_OFF,
        b2, nullptr, p_fx2, out, nullptr, nullptr, nullptr, CC, HID, CC, 0);
}